// round 1
// baseline (speedup 1.0000x reference)
#include <cuda_runtime.h>
#include <math.h>

#define BATCH 4
#define SEQ   4096
#define EMB   1024
#define HD    64
#define MTOT  (BATCH*SEQ)

// Scratch for projected q,k,v (device globals: allocation-rule-safe)
__device__ float g_q[MTOT*HD];
__device__ float g_k[MTOT*HD];
__device__ float g_v[MTOT*HD];

// ---------------------------------------------------------------------------
// Kernel 1: QKV projection. GEMM M=16384, K=1024, N=64, three weight matrices
// selected by blockIdx.y. BM=64, BN=64(=HD), BK=32, 256 threads, 4x4 microtile.
// ---------------------------------------------------------------------------
__global__ __launch_bounds__(256) void qkv_gemm(
    const float* __restrict__ x,
    const float* __restrict__ Wq,
    const float* __restrict__ Wk,
    const float* __restrict__ Wv)
{
    __shared__ float Xs[32][64];   // [k][m]
    __shared__ float Ws[32][64];   // [k][n]

    const float* W;
    float* out;
    if (blockIdx.y == 0)      { W = Wq; out = g_q; }
    else if (blockIdx.y == 1) { W = Wk; out = g_k; }
    else                      { W = Wv; out = g_v; }

    const int m0  = blockIdx.x * 64;
    const int tid = threadIdx.x;
    const int tx  = tid & 15;
    const int ty  = tid >> 4;

    // load indices
    const int xr = tid >> 2;          // 0..63 (row within tile)
    const int xk = (tid & 3) * 8;     // 0,8,16,24
    const int wk = tid >> 3;          // 0..31
    const int wn = (tid & 7) * 8;     // 0..56

    float acc[4][4] = {};

    for (int k0 = 0; k0 < EMB; k0 += 32) {
        const float* xsrc = x + (size_t)(m0 + xr) * EMB + k0 + xk;
        float4 a0 = *(const float4*)(xsrc);
        float4 a1 = *(const float4*)(xsrc + 4);
        const float* wsrc = W + (size_t)(k0 + wk) * HD + wn;
        float4 b0 = *(const float4*)(wsrc);
        float4 b1 = *(const float4*)(wsrc + 4);

        __syncthreads();   // previous iteration's compute finished
        Xs[xk+0][xr] = a0.x; Xs[xk+1][xr] = a0.y;
        Xs[xk+2][xr] = a0.z; Xs[xk+3][xr] = a0.w;
        Xs[xk+4][xr] = a1.x; Xs[xk+5][xr] = a1.y;
        Xs[xk+6][xr] = a1.z; Xs[xk+7][xr] = a1.w;
        *(float4*)&Ws[wk][wn]     = b0;
        *(float4*)&Ws[wk][wn + 4] = b1;
        __syncthreads();

        #pragma unroll
        for (int kk = 0; kk < 32; kk++) {
            float4 av = *(float4*)&Xs[kk][4*ty];
            float4 bv = *(float4*)&Ws[kk][4*tx];
            float a[4] = {av.x, av.y, av.z, av.w};
            float b[4] = {bv.x, bv.y, bv.z, bv.w};
            #pragma unroll
            for (int i = 0; i < 4; i++)
                #pragma unroll
                for (int j = 0; j < 4; j++)
                    acc[i][j] += a[i] * b[j];
        }
    }

    #pragma unroll
    for (int i = 0; i < 4; i++) {
        float4 r = make_float4(acc[i][0], acc[i][1], acc[i][2], acc[i][3]);
        *(float4*)(out + (size_t)(m0 + 4*ty + i) * HD + 4*tx) = r;
    }
}

// ---------------------------------------------------------------------------
// Kernel 2: causal flash attention, fp32.
// grid (32, BATCH), block 256. Each block processes TWO query tiles
// (bx and 63-bx) -> exactly 65 key tiles of work per block (load-balanced).
// Per tile: S = Q K^T (4x4 microtile), online softmax with 16-lane shuffle
// row reductions, P staged via SMEM, O += P V.
// ---------------------------------------------------------------------------
#define PS_LD 68

__global__ __launch_bounds__(256) void attn_kernel(float* __restrict__ out)
{
    extern __shared__ float smem[];
    float* Qt = smem;              // [h][r]  64*64
    float* Kt = Qt + 64*64;        // [h][s]  64*64
    float* Vs = Kt + 64*64;        // [s][h]  64*64
    float* Ps = Vs + 64*64;        // [r][s]  64*PS_LD

    const int b   = blockIdx.y;
    const int tid = threadIdx.x;
    const int tx  = tid & 15;
    const int ty  = tid >> 4;

    const float* qb = g_q + (size_t)b * SEQ * HD;
    const float* kb = g_k + (size_t)b * SEQ * HD;
    const float* vb = g_v + (size_t)b * SEQ * HD;
    float*       ob = out + (size_t)b * SEQ * HD;

    const int lr = tid >> 2;        // 0..63
    const int lh = (tid & 3) * 16;  // 0,16,32,48

    for (int pass = 0; pass < 2; pass++) {
        const int qt = (pass == 0) ? (int)blockIdx.x : 63 - (int)blockIdx.x;
        const int r0 = qt * 64;

        __syncthreads();  // all prior reads of Qt done before overwrite
        // Load Q tile transposed: Qt[h][r]
        #pragma unroll
        for (int c = 0; c < 4; c++) {
            float4 v = *(const float4*)(qb + (size_t)(r0 + lr) * HD + lh + 4*c);
            Qt[(lh + 4*c + 0) * 64 + lr] = v.x;
            Qt[(lh + 4*c + 1) * 64 + lr] = v.y;
            Qt[(lh + 4*c + 2) * 64 + lr] = v.z;
            Qt[(lh + 4*c + 3) * 64 + lr] = v.w;
        }

        float m_prev[4], lsum[4], o[4][4];
        #pragma unroll
        for (int i = 0; i < 4; i++) {
            m_prev[i] = -1e30f;
            lsum[i]   = 0.0f;
            #pragma unroll
            for (int j = 0; j < 4; j++) o[i][j] = 0.0f;
        }

        for (int jt = 0; jt <= qt; jt++) {
            const int s0 = jt * 64;
            __syncthreads();  // previous PV-GEMM reads of Kt/Vs/Ps done
            // Load K transposed + V straight
            #pragma unroll
            for (int c = 0; c < 4; c++) {
                float4 kv = *(const float4*)(kb + (size_t)(s0 + lr) * HD + lh + 4*c);
                Kt[(lh + 4*c + 0) * 64 + lr] = kv.x;
                Kt[(lh + 4*c + 1) * 64 + lr] = kv.y;
                Kt[(lh + 4*c + 2) * 64 + lr] = kv.z;
                Kt[(lh + 4*c + 3) * 64 + lr] = kv.w;
                *(float4*)&Vs[lr * 64 + lh + 4*c] =
                    *(const float4*)(vb + (size_t)(s0 + lr) * HD + lh + 4*c);
            }
            __syncthreads();

            // S = Q K^T  (this thread: rows 4ty.., cols 4tx..)
            float acc[4][4] = {};
            #pragma unroll 4
            for (int h = 0; h < 64; h++) {
                float4 av = *(float4*)&Qt[h * 64 + 4*ty];
                float4 bv = *(float4*)&Kt[h * 64 + 4*tx];
                float a[4] = {av.x, av.y, av.z, av.w};
                float bb[4] = {bv.x, bv.y, bv.z, bv.w};
                #pragma unroll
                for (int i = 0; i < 4; i++)
                    #pragma unroll
                    for (int j = 0; j < 4; j++)
                        acc[i][j] += a[i] * bb[j];
            }

            // scale + causal mask (diag tile only)
            const float scale = 0.03125f;  // 1/sqrt(1024)
            #pragma unroll
            for (int i = 0; i < 4; i++)
                #pragma unroll
                for (int j = 0; j < 4; j++) {
                    float s = acc[i][j] * scale;
                    if (jt == qt && (s0 + 4*tx + j) > (r0 + 4*ty + i)) s = -1e30f;
                    acc[i][j] = s;
                }

            // online softmax (row spread over 16 tx lanes -> half-warp shuffles)
            #pragma unroll
            for (int i = 0; i < 4; i++) {
                float rm = fmaxf(fmaxf(acc[i][0], acc[i][1]),
                                 fmaxf(acc[i][2], acc[i][3]));
                #pragma unroll
                for (int off = 8; off; off >>= 1)
                    rm = fmaxf(rm, __shfl_xor_sync(0xffffffffu, rm, off));
                float m_new = fmaxf(m_prev[i], rm);
                float alpha = __expf(m_prev[i] - m_new);
                float rs = 0.0f;
                #pragma unroll
                for (int j = 0; j < 4; j++) {
                    float p = __expf(acc[i][j] - m_new);
                    Ps[(4*ty + i) * PS_LD + 4*tx + j] = p;
                    rs += p;
                }
                #pragma unroll
                for (int off = 8; off; off >>= 1)
                    rs += __shfl_xor_sync(0xffffffffu, rs, off);
                lsum[i] = lsum[i] * alpha + rs;
                m_prev[i] = m_new;
                #pragma unroll
                for (int j = 0; j < 4; j++) o[i][j] *= alpha;
            }
            __syncthreads();  // Ps ready for everyone

            // O += P V
            #pragma unroll 4
            for (int s = 0; s < 64; s++) {
                float4 vv = *(float4*)&Vs[s * 64 + 4*tx];
                #pragma unroll
                for (int i = 0; i < 4; i++) {
                    float p = Ps[(4*ty + i) * PS_LD + s];
                    o[i][0] += p * vv.x;
                    o[i][1] += p * vv.y;
                    o[i][2] += p * vv.z;
                    o[i][3] += p * vv.w;
                }
            }
        }

        // normalize + store
        #pragma unroll
        for (int i = 0; i < 4; i++) {
            float inv = 1.0f / lsum[i];
            float4 r = make_float4(o[i][0]*inv, o[i][1]*inv, o[i][2]*inv, o[i][3]*inv);
            *(float4*)(ob + (size_t)(r0 + 4*ty + i) * HD + 4*tx) = r;
        }
    }
}

// ---------------------------------------------------------------------------
extern "C" void kernel_launch(void* const* d_in, const int* in_sizes, int n_in,
                              void* d_out, int out_size)
{
    const float* x  = (const float*)d_in[0];
    const float* Wq = (const float*)d_in[1];
    const float* Wk = (const float*)d_in[2];
    const float* Wv = (const float*)d_in[3];
    float* out = (float*)d_out;

    const int smem_bytes = (3 * 64 * 64 + 64 * PS_LD) * (int)sizeof(float);  // 66560
    cudaFuncSetAttribute(attn_kernel,
                         cudaFuncAttributeMaxDynamicSharedMemorySize, smem_bytes);

    qkv_gemm<<<dim3(MTOT / 64, 3), 256>>>(x, Wq, Wk, Wv);
    attn_kernel<<<dim3(32, BATCH), 256, smem_bytes>>>(out);
}

// round 2
// speedup vs baseline: 1.0001x; 1.0001x over previous
#include <cuda_runtime.h>
#include <math.h>

#define BATCH 4
#define SEQ   4096
#define EMB   1024
#define HD    64
#define MTOT  (BATCH*SEQ)

// Scratch for projected q,k,v (device globals: allocation-rule-safe)
__device__ float g_q[MTOT*HD];
__device__ float g_k[MTOT*HD];
__device__ float g_v[MTOT*HD];

// ---------------------------------------------------------------------------
// Kernel 1: QKV projection. GEMM M=16384, K=1024, N=64, three weight matrices
// selected by blockIdx.y. BM=64, BN=64(=HD), BK=32, 256 threads, 4x4 microtile.
// ---------------------------------------------------------------------------
__global__ __launch_bounds__(256) void qkv_gemm(
    const float* __restrict__ x,
    const float* __restrict__ Wq,
    const float* __restrict__ Wk,
    const float* __restrict__ Wv)
{
    __shared__ float Xs[32][64];   // [k][m]
    __shared__ float Ws[32][64];   // [k][n]

    const float* W;
    float* out;
    if (blockIdx.y == 0)      { W = Wq; out = g_q; }
    else if (blockIdx.y == 1) { W = Wk; out = g_k; }
    else                      { W = Wv; out = g_v; }

    const int m0  = blockIdx.x * 64;
    const int tid = threadIdx.x;
    const int tx  = tid & 15;
    const int ty  = tid >> 4;

    // load indices
    const int xr = tid >> 2;          // 0..63 (row within tile)
    const int xk = (tid & 3) * 8;     // 0,8,16,24
    const int wk = tid >> 3;          // 0..31
    const int wn = (tid & 7) * 8;     // 0..56

    float acc[4][4] = {};

    for (int k0 = 0; k0 < EMB; k0 += 32) {
        const float* xsrc = x + (size_t)(m0 + xr) * EMB + k0 + xk;
        float4 a0 = *(const float4*)(xsrc);
        float4 a1 = *(const float4*)(xsrc + 4);
        const float* wsrc = W + (size_t)(k0 + wk) * HD + wn;
        float4 b0 = *(const float4*)(wsrc);
        float4 b1 = *(const float4*)(wsrc + 4);

        __syncthreads();   // previous iteration's compute finished
        Xs[xk+0][xr] = a0.x; Xs[xk+1][xr] = a0.y;
        Xs[xk+2][xr] = a0.z; Xs[xk+3][xr] = a0.w;
        Xs[xk+4][xr] = a1.x; Xs[xk+5][xr] = a1.y;
        Xs[xk+6][xr] = a1.z; Xs[xk+7][xr] = a1.w;
        *(float4*)&Ws[wk][wn]     = b0;
        *(float4*)&Ws[wk][wn + 4] = b1;
        __syncthreads();

        #pragma unroll
        for (int kk = 0; kk < 32; kk++) {
            float4 av = *(float4*)&Xs[kk][4*ty];
            float4 bv = *(float4*)&Ws[kk][4*tx];
            float a[4] = {av.x, av.y, av.z, av.w};
            float b[4] = {bv.x, bv.y, bv.z, bv.w};
            #pragma unroll
            for (int i = 0; i < 4; i++)
                #pragma unroll
                for (int j = 0; j < 4; j++)
                    acc[i][j] += a[i] * b[j];
        }
    }

    #pragma unroll
    for (int i = 0; i < 4; i++) {
        float4 r = make_float4(acc[i][0], acc[i][1], acc[i][2], acc[i][3]);
        *(float4*)(out + (size_t)(m0 + 4*ty + i) * HD + 4*tx) = r;
    }
}

// ---------------------------------------------------------------------------
// Kernel 2: causal flash attention, fp32.
// grid (32, BATCH), block 256. Each block processes TWO query tiles
// (bx and 63-bx) -> exactly 65 key tiles of work per block (load-balanced).
// Per tile: S = Q K^T (4x4 microtile), online softmax with 16-lane shuffle
// row reductions, P staged via SMEM, O += P V.
// ---------------------------------------------------------------------------
#define PS_LD 68

__global__ __launch_bounds__(256) void attn_kernel(float* __restrict__ out)
{
    extern __shared__ float smem[];
    float* Qt = smem;              // [h][r]  64*64
    float* Kt = Qt + 64*64;        // [h][s]  64*64
    float* Vs = Kt + 64*64;        // [s][h]  64*64
    float* Ps = Vs + 64*64;        // [r][s]  64*PS_LD

    const int b   = blockIdx.y;
    const int tid = threadIdx.x;
    const int tx  = tid & 15;
    const int ty  = tid >> 4;

    const float* qb = g_q + (size_t)b * SEQ * HD;
    const float* kb = g_k + (size_t)b * SEQ * HD;
    const float* vb = g_v + (size_t)b * SEQ * HD;
    float*       ob = out + (size_t)b * SEQ * HD;

    const int lr = tid >> 2;        // 0..63
    const int lh = (tid & 3) * 16;  // 0,16,32,48

    for (int pass = 0; pass < 2; pass++) {
        const int qt = (pass == 0) ? (int)blockIdx.x : 63 - (int)blockIdx.x;
        const int r0 = qt * 64;

        __syncthreads();  // all prior reads of Qt done before overwrite
        // Load Q tile transposed: Qt[h][r]
        #pragma unroll
        for (int c = 0; c < 4; c++) {
            float4 v = *(const float4*)(qb + (size_t)(r0 + lr) * HD + lh + 4*c);
            Qt[(lh + 4*c + 0) * 64 + lr] = v.x;
            Qt[(lh + 4*c + 1) * 64 + lr] = v.y;
            Qt[(lh + 4*c + 2) * 64 + lr] = v.z;
            Qt[(lh + 4*c + 3) * 64 + lr] = v.w;
        }

        float m_prev[4], lsum[4], o[4][4];
        #pragma unroll
        for (int i = 0; i < 4; i++) {
            m_prev[i] = -1e30f;
            lsum[i]   = 0.0f;
            #pragma unroll
            for (int j = 0; j < 4; j++) o[i][j] = 0.0f;
        }

        for (int jt = 0; jt <= qt; jt++) {
            const int s0 = jt * 64;
            __syncthreads();  // previous PV-GEMM reads of Kt/Vs/Ps done
            // Load K transposed + V straight
            #pragma unroll
            for (int c = 0; c < 4; c++) {
                float4 kv = *(const float4*)(kb + (size_t)(s0 + lr) * HD + lh + 4*c);
                Kt[(lh + 4*c + 0) * 64 + lr] = kv.x;
                Kt[(lh + 4*c + 1) * 64 + lr] = kv.y;
                Kt[(lh + 4*c + 2) * 64 + lr] = kv.z;
                Kt[(lh + 4*c + 3) * 64 + lr] = kv.w;
                *(float4*)&Vs[lr * 64 + lh + 4*c] =
                    *(const float4*)(vb + (size_t)(s0 + lr) * HD + lh + 4*c);
            }
            __syncthreads();

            // S = Q K^T  (this thread: rows 4ty.., cols 4tx..)
            float acc[4][4] = {};
            #pragma unroll 4
            for (int h = 0; h < 64; h++) {
                float4 av = *(float4*)&Qt[h * 64 + 4*ty];
                float4 bv = *(float4*)&Kt[h * 64 + 4*tx];
                float a[4] = {av.x, av.y, av.z, av.w};
                float bb[4] = {bv.x, bv.y, bv.z, bv.w};
                #pragma unroll
                for (int i = 0; i < 4; i++)
                    #pragma unroll
                    for (int j = 0; j < 4; j++)
                        acc[i][j] += a[i] * bb[j];
            }

            // scale + causal mask (diag tile only)
            const float scale = 0.03125f;  // 1/sqrt(1024)
            #pragma unroll
            for (int i = 0; i < 4; i++)
                #pragma unroll
                for (int j = 0; j < 4; j++) {
                    float s = acc[i][j] * scale;
                    if (jt == qt && (s0 + 4*tx + j) > (r0 + 4*ty + i)) s = -1e30f;
                    acc[i][j] = s;
                }

            // online softmax (row spread over 16 tx lanes -> half-warp shuffles)
            #pragma unroll
            for (int i = 0; i < 4; i++) {
                float rm = fmaxf(fmaxf(acc[i][0], acc[i][1]),
                                 fmaxf(acc[i][2], acc[i][3]));
                #pragma unroll
                for (int off = 8; off; off >>= 1)
                    rm = fmaxf(rm, __shfl_xor_sync(0xffffffffu, rm, off));
                float m_new = fmaxf(m_prev[i], rm);
                float alpha = __expf(m_prev[i] - m_new);
                float rs = 0.0f;
                #pragma unroll
                for (int j = 0; j < 4; j++) {
                    float p = __expf(acc[i][j] - m_new);
                    Ps[(4*ty + i) * PS_LD + 4*tx + j] = p;
                    rs += p;
                }
                #pragma unroll
                for (int off = 8; off; off >>= 1)
                    rs += __shfl_xor_sync(0xffffffffu, rs, off);
                lsum[i] = lsum[i] * alpha + rs;
                m_prev[i] = m_new;
                #pragma unroll
                for (int j = 0; j < 4; j++) o[i][j] *= alpha;
            }
            __syncthreads();  // Ps ready for everyone

            // O += P V
            #pragma unroll 4
            for (int s = 0; s < 64; s++) {
                float4 vv = *(float4*)&Vs[s * 64 + 4*tx];
                #pragma unroll
                for (int i = 0; i < 4; i++) {
                    float p = Ps[(4*ty + i) * PS_LD + s];
                    o[i][0] += p * vv.x;
                    o[i][1] += p * vv.y;
                    o[i][2] += p * vv.z;
                    o[i][3] += p * vv.w;
                }
            }
        }

        // normalize + store
        #pragma unroll
        for (int i = 0; i < 4; i++) {
            float inv = 1.0f / lsum[i];
            float4 r = make_float4(o[i][0]*inv, o[i][1]*inv, o[i][2]*inv, o[i][3]*inv);
            *(float4*)(ob + (size_t)(r0 + 4*ty + i) * HD + 4*tx) = r;
        }
    }
}

// ---------------------------------------------------------------------------
extern "C" void kernel_launch(void* const* d_in, const int* in_sizes, int n_in,
                              void* d_out, int out_size)
{
    const float* x  = (const float*)d_in[0];
    const float* Wq = (const float*)d_in[1];
    const float* Wk = (const float*)d_in[2];
    const float* Wv = (const float*)d_in[3];
    float* out = (float*)d_out;

    const int smem_bytes = (3 * 64 * 64 + 64 * PS_LD) * (int)sizeof(float);  // 66560
    cudaFuncSetAttribute(attn_kernel,
                         cudaFuncAttributeMaxDynamicSharedMemorySize, smem_bytes);

    qkv_gemm<<<dim3(MTOT / 64, 3), 256>>>(x, Wq, Wk, Wv);
    attn_kernel<<<dim3(32, BATCH), 256, smem_bytes>>>(out);
}

// round 8
// speedup vs baseline: 1.4033x; 1.4031x over previous
#include <cuda_runtime.h>
#include <cuda_bf16.h>
#include <stdint.h>
#include <math.h>

#define BATCH 4
#define SEQ   4096
#define EMB   1024
#define HD    64
#define MTOT  (BATCH*SEQ)

// Scratch for projected q,k,v (device globals: allocation-rule-safe)
__device__ float g_q[MTOT*HD];
__device__ float g_k[MTOT*HD];
__device__ float g_v[MTOT*HD];

// Single extern shared symbol (char) — cast per kernel.
extern __shared__ char hx_smem[];

// ---------------------------------------------------------------------------
// Helpers
// ---------------------------------------------------------------------------
__device__ __forceinline__ uint32_t smem_u32(const void* p) {
    uint32_t a;
    asm("{ .reg .u64 t; cvta.to.shared.u64 t, %1; cvt.u32.u64 %0, t; }"
        : "=r"(a) : "l"(p));
    return a;
}

__device__ __forceinline__ void ldsm_x4(uint32_t* r, uint32_t addr) {
    asm volatile("ldmatrix.sync.aligned.m8n8.x4.shared.b16 {%0,%1,%2,%3}, [%4];"
        : "=r"(r[0]), "=r"(r[1]), "=r"(r[2]), "=r"(r[3]) : "r"(addr));
}

// D += A @ B : m16n8k16, bf16 in, fp32 accum
__device__ __forceinline__ void mma16816(float* d, const uint32_t* a,
                                         const uint32_t* b) {
    asm volatile("mma.sync.aligned.m16n8k16.row.col.f32.bf16.bf16.f32 "
        "{%0,%1,%2,%3}, {%4,%5,%6,%7}, {%8,%9}, {%0,%1,%2,%3};"
        : "+f"(d[0]), "+f"(d[1]), "+f"(d[2]), "+f"(d[3])
        : "r"(a[0]), "r"(a[1]), "r"(a[2]), "r"(a[3]), "r"(b[0]), "r"(b[1]));
}

// ---------------------------------------------------------------------------
// Kernel 1: QKV projection via warp-level bf16 MMA with hi/lo split.
// out[16384x64] = X[16384x1024] @ W[1024x64], W in {Wq,Wk,Wv}.
// Grid 128 CTAs (BM=128 rows), 256 threads (8 warps x m16). BK=64.
// SMEM rows padded to 144B -> conflict-free ldmatrix.
// ---------------------------------------------------------------------------
#define BROW 144                       // bytes per smem row (64 bf16 + pad)
#define QOFF_AH 0
#define QOFF_AL (128*BROW)             // 18432
#define QOFF_B  (2*128*BROW)           // 36864; 6 tiles of 64*BROW=9216
#define BTILE   (64*BROW)
#define QKV_SMEM (QOFF_B + 6*BTILE)    // 92160

__global__ __launch_bounds__(256) void qkv_mma(
    const float* __restrict__ x,
    const float* __restrict__ Wq,
    const float* __restrict__ Wk,
    const float* __restrict__ Wv)
{
    char* smem = hx_smem;
    const uint32_t sb = smem_u32(smem);
    const int tid  = threadIdx.x;
    const int wid  = tid >> 5;
    const int lane = tid & 31;
    const int m0   = blockIdx.x * 128;

    const float* Ws[3] = {Wq, Wk, Wv};

    // ldmatrix lane address components
    const int a_row  = lane & 15;
    const int a_koff = (lane >> 4) * 8;          // bf16 elems
    const int b_q    = lane >> 3;
    const int b_r    = lane & 7;
    const int b_nloc = (b_q >> 1) * 8 + b_r;     // n within 16-wide pair
    const int b_koff = (b_q & 1) * 8;

    float acc[3][8][4] = {};

    // W-loader indices: 256 threads cover n=0..63 x 4 k-rows per step
    const int wn = tid & 63;
    const int wk0 = tid >> 6;       // 0..3

    #pragma unroll 1
    for (int c = 0; c < 16; c++) {
        __syncthreads();   // previous chunk's LDSM reads complete

        // ---- A chunk: X[m0..+127][c*64..+63] -> hi/lo bf16 smem ----
        #pragma unroll
        for (int i = 0; i < 8; i++) {
            int j  = tid + i * 256;          // 0..2047 float4s
            int r  = j >> 4;
            int c4 = (j & 15) * 4;
            float4 v = *(const float4*)(x + (size_t)(m0 + r) * EMB + c * 64 + c4);
            __nv_bfloat16 h0 = __float2bfloat16(v.x);
            __nv_bfloat16 h1 = __float2bfloat16(v.y);
            __nv_bfloat16 h2 = __float2bfloat16(v.z);
            __nv_bfloat16 h3 = __float2bfloat16(v.w);
            __nv_bfloat162 hA = {h0, h1}, hB = {h2, h3};
            __nv_bfloat162 lA = {__float2bfloat16(v.x - __bfloat162float(h0)),
                                 __float2bfloat16(v.y - __bfloat162float(h1))};
            __nv_bfloat162 lB = {__float2bfloat16(v.z - __bfloat162float(h2)),
                                 __float2bfloat16(v.w - __bfloat162float(h3))};
            uint32_t off = (uint32_t)(r * BROW + c4 * 2);
            *(uint2*)(smem + QOFF_AH + off) =
                make_uint2(*(uint32_t*)&hA, *(uint32_t*)&hB);
            *(uint2*)(smem + QOFF_AL + off) =
                make_uint2(*(uint32_t*)&lA, *(uint32_t*)&lB);
        }

        // ---- B chunks: W[c*64+k][n] -> Bs[n][k] hi/lo bf16 ----
        #pragma unroll
        for (int o = 0; o < 3; o++) {
            const float* W = Ws[o];
            char* bh = smem + QOFF_B + (o * 2 + 0) * BTILE;
            char* bl = smem + QOFF_B + (o * 2 + 1) * BTILE;
            #pragma unroll 4
            for (int i = 0; i < 16; i++) {
                int kl = i * 4 + wk0;
                float f = W[(size_t)(c * 64 + kl) * HD + wn];
                __nv_bfloat16 h = __float2bfloat16(f);
                __nv_bfloat16 l = __float2bfloat16(f - __bfloat162float(h));
                uint32_t off = (uint32_t)(wn * BROW + kl * 2);
                *(__nv_bfloat16*)(bh + off) = h;
                *(__nv_bfloat16*)(bl + off) = l;
            }
        }
        __syncthreads();

        // ---- A fragments: 2 splits x 4 k-steps ----
        uint32_t afr[2][4][4];
        #pragma unroll
        for (int spl = 0; spl < 2; spl++)
            #pragma unroll
            for (int s = 0; s < 4; s++)
                ldsm_x4(afr[spl][s],
                        sb + (spl ? QOFF_AL : QOFF_AH) +
                        (uint32_t)((wid * 16 + a_row) * BROW +
                                   (s * 16 + a_koff) * 2));

        // ---- MMAs: Xh@Wh + Xl@Wh + Xh@Wl ----
        #pragma unroll
        for (int o = 0; o < 3; o++) {
            uint32_t bhb = sb + QOFF_B + (o * 2 + 0) * BTILE;
            uint32_t blb = sb + QOFF_B + (o * 2 + 1) * BTILE;
            #pragma unroll
            for (int s = 0; s < 4; s++) {
                #pragma unroll
                for (int p = 0; p < 4; p++) {
                    uint32_t boff = (uint32_t)((p * 16 + b_nloc) * BROW +
                                               (s * 16 + b_koff) * 2);
                    uint32_t bf[4];
                    ldsm_x4(bf, bhb + boff);
                    mma16816(acc[o][2*p],   afr[0][s], bf);
                    mma16816(acc[o][2*p+1], afr[0][s], bf + 2);
                    mma16816(acc[o][2*p],   afr[1][s], bf);
                    mma16816(acc[o][2*p+1], afr[1][s], bf + 2);
                    ldsm_x4(bf, blb + boff);
                    mma16816(acc[o][2*p],   afr[0][s], bf);
                    mma16816(acc[o][2*p+1], afr[0][s], bf + 2);
                }
            }
        }
    }

    // ---- epilogue: c-frag -> global ----
    float* outs[3] = {g_q, g_k, g_v};
    const int g  = lane >> 2;
    const int tg = lane & 3;
    #pragma unroll
    for (int o = 0; o < 3; o++) {
        float* out = outs[o];
        #pragma unroll
        for (int nt = 0; nt < 8; nt++) {
            int mrow = m0 + wid * 16 + g;
            int ncol = nt * 8 + tg * 2;
            *(float2*)&out[(size_t)mrow * HD + ncol] =
                make_float2(acc[o][nt][0], acc[o][nt][1]);
            *(float2*)&out[(size_t)(mrow + 8) * HD + ncol] =
                make_float2(acc[o][nt][2], acc[o][nt][3]);
        }
    }
}

// ---------------------------------------------------------------------------
// Kernel 2: causal flash attention, fp32, 512 threads.
// Block bx handles q-tiles bx and 63-bx (2 passes). The two 256-thread halves
// process even/odd key tiles of the SAME q-tile, then merge (m, l, O).
// ---------------------------------------------------------------------------
#define PS_LD 68
#define REGION 12544   // floats: Kt 4096 + Vs 4096 + Ps 64*68

__global__ __launch_bounds__(512) void attn_kernel(float* __restrict__ out)
{
    float* smem = (float*)hx_smem;
    float* Qt = smem;                                  // [h][r] 64x64, shared
    const int tid  = threadIdx.x;
    const int half = tid >> 8;
    const int ltid = tid & 255;
    const int tx   = ltid & 15;
    const int ty   = ltid >> 4;

    float* R  = smem + 4096 + half * REGION;
    float* Kt = R;                // [h][s] 64x64
    float* Vs = R + 4096;         // [s][h] 64x64
    float* Ps = R + 8192;         // [r][s] 64xPS_LD
    float* R1Kt = smem + 4096 + REGION;          // half1 Kt (merge O buffer)
    float* R1Vs = R1Kt + 4096;                   // half1 Vs (merge m/l buffer)

    const int b = blockIdx.y;
    const float* qb = g_q + (size_t)b * SEQ * HD;
    const float* kb = g_k + (size_t)b * SEQ * HD;
    const float* vb = g_v + (size_t)b * SEQ * HD;
    float*       ob = out + (size_t)b * SEQ * HD;

    const int lr = ltid >> 2;        // 0..63
    const int lh = (ltid & 3) * 16;  // 0,16,32,48

    for (int pass = 0; pass < 2; pass++) {
        const int qt = (pass == 0) ? (int)blockIdx.x : 63 - (int)blockIdx.x;
        const int r0 = qt * 64;

        __syncthreads();   // all reads of Qt / merge buffers from prev pass done
        if (half == 0) {
            #pragma unroll
            for (int c = 0; c < 4; c++) {
                float4 v = *(const float4*)(qb + (size_t)(r0 + lr) * HD + lh + 4*c);
                Qt[(lh + 4*c + 0) * 64 + lr] = v.x;
                Qt[(lh + 4*c + 1) * 64 + lr] = v.y;
                Qt[(lh + 4*c + 2) * 64 + lr] = v.z;
                Qt[(lh + 4*c + 3) * 64 + lr] = v.w;
            }
        }
        __syncthreads();   // Qt ready for both halves

        float m_prev[4], lsum[4], o[4][4];
        #pragma unroll
        for (int i = 0; i < 4; i++) {
            m_prev[i] = -1e30f; lsum[i] = 0.0f;
            #pragma unroll
            for (int j = 0; j < 4; j++) o[i][j] = 0.0f;
        }

        for (int jt = half; jt <= qt; jt += 2) {
            const int s0 = jt * 64;
            asm volatile("bar.sync %0, 256;" :: "r"(half + 1) : "memory");
            #pragma unroll
            for (int c = 0; c < 4; c++) {
                float4 kv = *(const float4*)(kb + (size_t)(s0 + lr) * HD + lh + 4*c);
                Kt[(lh + 4*c + 0) * 64 + lr] = kv.x;
                Kt[(lh + 4*c + 1) * 64 + lr] = kv.y;
                Kt[(lh + 4*c + 2) * 64 + lr] = kv.z;
                Kt[(lh + 4*c + 3) * 64 + lr] = kv.w;
                *(float4*)&Vs[lr * 64 + lh + 4*c] =
                    *(const float4*)(vb + (size_t)(s0 + lr) * HD + lh + 4*c);
            }
            asm volatile("bar.sync %0, 256;" :: "r"(half + 1) : "memory");

            // S = Q K^T
            float acc[4][4] = {};
            #pragma unroll 4
            for (int h = 0; h < 64; h++) {
                float4 av = *(float4*)&Qt[h * 64 + 4*ty];
                float4 bv = *(float4*)&Kt[h * 64 + 4*tx];
                float a[4]  = {av.x, av.y, av.z, av.w};
                float bb[4] = {bv.x, bv.y, bv.z, bv.w};
                #pragma unroll
                for (int i = 0; i < 4; i++)
                    #pragma unroll
                    for (int j = 0; j < 4; j++)
                        acc[i][j] += a[i] * bb[j];
            }

            const float scale = 0.03125f;  // 1/sqrt(1024)
            #pragma unroll
            for (int i = 0; i < 4; i++)
                #pragma unroll
                for (int j = 0; j < 4; j++) {
                    float s = acc[i][j] * scale;
                    if (jt == qt && (s0 + 4*tx + j) > (r0 + 4*ty + i)) s = -1e30f;
                    acc[i][j] = s;
                }

            #pragma unroll
            for (int i = 0; i < 4; i++) {
                float rm = fmaxf(fmaxf(acc[i][0], acc[i][1]),
                                 fmaxf(acc[i][2], acc[i][3]));
                #pragma unroll
                for (int off = 8; off; off >>= 1)
                    rm = fmaxf(rm, __shfl_xor_sync(0xffffffffu, rm, off));
                float m_new = fmaxf(m_prev[i], rm);
                float alpha = __expf(m_prev[i] - m_new);
                float rs = 0.0f;
                #pragma unroll
                for (int j = 0; j < 4; j++) {
                    float p = __expf(acc[i][j] - m_new);
                    Ps[(4*ty + i) * PS_LD + 4*tx + j] = p;
                    rs += p;
                }
                #pragma unroll
                for (int off = 8; off; off >>= 1)
                    rs += __shfl_xor_sync(0xffffffffu, rs, off);
                lsum[i] = lsum[i] * alpha + rs;
                m_prev[i] = m_new;
                #pragma unroll
                for (int j = 0; j < 4; j++) o[i][j] *= alpha;
            }
            asm volatile("bar.sync %0, 256;" :: "r"(half + 1) : "memory");

            #pragma unroll 4
            for (int s = 0; s < 64; s++) {
                float4 vv = *(float4*)&Vs[s * 64 + 4*tx];
                #pragma unroll
                for (int i = 0; i < 4; i++) {
                    float p = Ps[(4*ty + i) * PS_LD + s];
                    o[i][0] += p * vv.x;
                    o[i][1] += p * vv.y;
                    o[i][2] += p * vv.z;
                    o[i][3] += p * vv.w;
                }
            }
        }

        // half1 publishes its state for the merge
        if (half == 1) {
            asm volatile("bar.sync 2, 256;" ::: "memory");  // all half1 PV reads done
            #pragma unroll
            for (int i = 0; i < 4; i++) {
                #pragma unroll
                for (int j = 0; j < 4; j++)
                    R1Kt[(4*ty + i) * 64 + 4*tx + j] = o[i][j];
                if (tx == 0) {
                    R1Vs[4*ty + i]      = m_prev[i];
                    R1Vs[64 + 4*ty + i] = lsum[i];
                }
            }
        }
        __syncthreads();   // half1 state visible

        if (half == 0) {
            #pragma unroll
            for (int i = 0; i < 4; i++) {
                float m1 = R1Vs[4*ty + i];
                float l1 = R1Vs[64 + 4*ty + i];
                float mm = fmaxf(m_prev[i], m1);
                float e0 = __expf(m_prev[i] - mm);
                float e1 = __expf(m1 - mm);
                float inv = 1.0f / (lsum[i] * e0 + l1 * e1);
                float4 r;
                r.x = (o[i][0]*e0 + R1Kt[(4*ty+i)*64 + 4*tx + 0]*e1) * inv;
                r.y = (o[i][1]*e0 + R1Kt[(4*ty+i)*64 + 4*tx + 1]*e1) * inv;
                r.z = (o[i][2]*e0 + R1Kt[(4*ty+i)*64 + 4*tx + 2]*e1) * inv;
                r.w = (o[i][3]*e0 + R1Kt[(4*ty+i)*64 + 4*tx + 3]*e1) * inv;
                *(float4*)(ob + (size_t)(r0 + 4*ty + i) * HD + 4*tx) = r;
            }
        }
    }
}

// ---------------------------------------------------------------------------
extern "C" void kernel_launch(void* const* d_in, const int* in_sizes, int n_in,
                              void* d_out, int out_size)
{
    const float* x  = (const float*)d_in[0];
    const float* Wq = (const float*)d_in[1];
    const float* Wk = (const float*)d_in[2];
    const float* Wv = (const float*)d_in[3];
    float* out = (float*)d_out;

    cudaFuncSetAttribute(qkv_mma,
                         cudaFuncAttributeMaxDynamicSharedMemorySize, QKV_SMEM);
    const int attn_smem = (4096 + 2 * REGION) * (int)sizeof(float);  // 116736
    cudaFuncSetAttribute(attn_kernel,
                         cudaFuncAttributeMaxDynamicSharedMemorySize, attn_smem);

    qkv_mma<<<MTOT / 128, 256, QKV_SMEM>>>(x, Wq, Wk, Wv);
    attn_kernel<<<dim3(32, BATCH), 512, attn_smem>>>(out);
}

// round 9
// speedup vs baseline: 2.2429x; 1.5983x over previous
#include <cuda_runtime.h>
#include <cuda_bf16.h>
#include <stdint.h>
#include <math.h>

#define BATCH 4
#define SEQ   4096
#define EMB   1024
#define HD    64
#define MTOT  (BATCH*SEQ)

// bf16 hi/lo projected Q,K,V (device globals: allocation-rule-safe)
__device__ __nv_bfloat16 g_qh[MTOT*HD];
__device__ __nv_bfloat16 g_ql[MTOT*HD];
__device__ __nv_bfloat16 g_kh[MTOT*HD];
__device__ __nv_bfloat16 g_kl[MTOT*HD];
__device__ __nv_bfloat16 g_vh[MTOT*HD];
__device__ __nv_bfloat16 g_vl[MTOT*HD];

// Single extern shared symbol (char) — cast per kernel.
extern __shared__ char hx_smem[];

// ---------------------------------------------------------------------------
// Helpers
// ---------------------------------------------------------------------------
__device__ __forceinline__ uint32_t smem_u32(const void* p) {
    uint32_t a;
    asm("{ .reg .u64 t; cvta.to.shared.u64 t, %1; cvt.u32.u64 %0, t; }"
        : "=r"(a) : "l"(p));
    return a;
}

__device__ __forceinline__ void ldsm_x4(uint32_t* r, uint32_t addr) {
    asm volatile("ldmatrix.sync.aligned.m8n8.x4.shared.b16 {%0,%1,%2,%3}, [%4];"
        : "=r"(r[0]), "=r"(r[1]), "=r"(r[2]), "=r"(r[3]) : "r"(addr));
}
__device__ __forceinline__ void ldsm_x4_t(uint32_t* r, uint32_t addr) {
    asm volatile("ldmatrix.sync.aligned.m8n8.x4.trans.shared.b16 {%0,%1,%2,%3}, [%4];"
        : "=r"(r[0]), "=r"(r[1]), "=r"(r[2]), "=r"(r[3]) : "r"(addr));
}

// D += A @ B : m16n8k16, bf16 in, fp32 accum
__device__ __forceinline__ void mma16816(float* d, const uint32_t* a,
                                         const uint32_t* b) {
    asm volatile("mma.sync.aligned.m16n8k16.row.col.f32.bf16.bf16.f32 "
        "{%0,%1,%2,%3}, {%4,%5,%6,%7}, {%8,%9}, {%0,%1,%2,%3};"
        : "+f"(d[0]), "+f"(d[1]), "+f"(d[2]), "+f"(d[3])
        : "r"(a[0]), "r"(a[1]), "r"(a[2]), "r"(a[3]), "r"(b[0]), "r"(b[1]));
}

__device__ __forceinline__ uint32_t pack_bf2(float a, float b) {
    __nv_bfloat162 t = __floats2bfloat162_rn(a, b);
    return *(uint32_t*)&t;
}

// ---------------------------------------------------------------------------
// Kernel 1: QKV projection via warp-level bf16 MMA with hi/lo split.
// Writes bf16 hi/lo q,k,v to device globals.
// Grid 128 CTAs (BM=128 rows), 256 threads (8 warps x m16). BK=64.
// ---------------------------------------------------------------------------
#define BROW 144                       // bytes per smem row (64 bf16 + pad)
#define QOFF_AH 0
#define QOFF_AL (128*BROW)             // 18432
#define QOFF_B  (2*128*BROW)           // 36864; 6 tiles of 64*BROW=9216
#define BTILE   (64*BROW)
#define QKV_SMEM (QOFF_B + 6*BTILE)    // 92160

__global__ __launch_bounds__(256) void qkv_mma(
    const float* __restrict__ x,
    const float* __restrict__ Wq,
    const float* __restrict__ Wk,
    const float* __restrict__ Wv)
{
    char* smem = hx_smem;
    const uint32_t sb = smem_u32(smem);
    const int tid  = threadIdx.x;
    const int wid  = tid >> 5;
    const int lane = tid & 31;
    const int m0   = blockIdx.x * 128;

    const float* Ws[3] = {Wq, Wk, Wv};

    // ldmatrix lane address components
    const int a_row  = lane & 15;
    const int a_koff = (lane >> 4) * 8;          // bf16 elems
    const int b_q    = lane >> 3;
    const int b_r    = lane & 7;
    const int b_nloc = (b_q >> 1) * 8 + b_r;     // n within 16-wide pair
    const int b_koff = (b_q & 1) * 8;

    float acc[3][8][4] = {};

    // W-loader indices: 256 threads cover n=0..63 x 4 k-rows per step
    const int wn = tid & 63;
    const int wk0 = tid >> 6;       // 0..3

    #pragma unroll 1
    for (int c = 0; c < 16; c++) {
        __syncthreads();   // previous chunk's LDSM reads complete

        // ---- A chunk: X[m0..+127][c*64..+63] -> hi/lo bf16 smem ----
        #pragma unroll
        for (int i = 0; i < 8; i++) {
            int j  = tid + i * 256;          // 0..2047 float4s
            int r  = j >> 4;
            int c4 = (j & 15) * 4;
            float4 v = *(const float4*)(x + (size_t)(m0 + r) * EMB + c * 64 + c4);
            __nv_bfloat16 h0 = __float2bfloat16(v.x);
            __nv_bfloat16 h1 = __float2bfloat16(v.y);
            __nv_bfloat16 h2 = __float2bfloat16(v.z);
            __nv_bfloat16 h3 = __float2bfloat16(v.w);
            __nv_bfloat162 hA = {h0, h1}, hB = {h2, h3};
            __nv_bfloat162 lA = {__float2bfloat16(v.x - __bfloat162float(h0)),
                                 __float2bfloat16(v.y - __bfloat162float(h1))};
            __nv_bfloat162 lB = {__float2bfloat16(v.z - __bfloat162float(h2)),
                                 __float2bfloat16(v.w - __bfloat162float(h3))};
            uint32_t off = (uint32_t)(r * BROW + c4 * 2);
            *(uint2*)(smem + QOFF_AH + off) =
                make_uint2(*(uint32_t*)&hA, *(uint32_t*)&hB);
            *(uint2*)(smem + QOFF_AL + off) =
                make_uint2(*(uint32_t*)&lA, *(uint32_t*)&lB);
        }

        // ---- B chunks: W[c*64+k][n] -> Bs[n][k] hi/lo bf16 ----
        #pragma unroll
        for (int o = 0; o < 3; o++) {
            const float* W = Ws[o];
            char* bh = smem + QOFF_B + (o * 2 + 0) * BTILE;
            char* bl = smem + QOFF_B + (o * 2 + 1) * BTILE;
            #pragma unroll 4
            for (int i = 0; i < 16; i++) {
                int kl = i * 4 + wk0;
                float f = W[(size_t)(c * 64 + kl) * HD + wn];
                __nv_bfloat16 h = __float2bfloat16(f);
                __nv_bfloat16 l = __float2bfloat16(f - __bfloat162float(h));
                uint32_t off = (uint32_t)(wn * BROW + kl * 2);
                *(__nv_bfloat16*)(bh + off) = h;
                *(__nv_bfloat16*)(bl + off) = l;
            }
        }
        __syncthreads();

        // ---- A fragments: 2 splits x 4 k-steps ----
        uint32_t afr[2][4][4];
        #pragma unroll
        for (int spl = 0; spl < 2; spl++)
            #pragma unroll
            for (int s = 0; s < 4; s++)
                ldsm_x4(afr[spl][s],
                        sb + (spl ? QOFF_AL : QOFF_AH) +
                        (uint32_t)((wid * 16 + a_row) * BROW +
                                   (s * 16 + a_koff) * 2));

        // ---- MMAs: Xh@Wh + Xl@Wh + Xh@Wl ----
        #pragma unroll
        for (int o = 0; o < 3; o++) {
            uint32_t bhb = sb + QOFF_B + (o * 2 + 0) * BTILE;
            uint32_t blb = sb + QOFF_B + (o * 2 + 1) * BTILE;
            #pragma unroll
            for (int s = 0; s < 4; s++) {
                #pragma unroll
                for (int p = 0; p < 4; p++) {
                    uint32_t boff = (uint32_t)((p * 16 + b_nloc) * BROW +
                                               (s * 16 + b_koff) * 2);
                    uint32_t bf[4];
                    ldsm_x4(bf, bhb + boff);
                    mma16816(acc[o][2*p],   afr[0][s], bf);
                    mma16816(acc[o][2*p+1], afr[0][s], bf + 2);
                    mma16816(acc[o][2*p],   afr[1][s], bf);
                    mma16816(acc[o][2*p+1], afr[1][s], bf + 2);
                    ldsm_x4(bf, blb + boff);
                    mma16816(acc[o][2*p],   afr[0][s], bf);
                    mma16816(acc[o][2*p+1], afr[0][s], bf + 2);
                }
            }
        }
    }

    // ---- epilogue: c-frags -> bf16 hi/lo globals ----
    __nv_bfloat16* OH[3] = {g_qh, g_kh, g_vh};
    __nv_bfloat16* OL[3] = {g_ql, g_kl, g_vl};
    const int g  = lane >> 2;
    const int tg = lane & 3;
    #pragma unroll
    for (int o = 0; o < 3; o++) {
        #pragma unroll
        for (int nt = 0; nt < 8; nt++) {
            int mrow = m0 + wid * 16 + g;
            int ncol = nt * 8 + tg * 2;
            float c0 = acc[o][nt][0], c1 = acc[o][nt][1];
            float c2 = acc[o][nt][2], c3 = acc[o][nt][3];
            __nv_bfloat162 h01 = __floats2bfloat162_rn(c0, c1);
            __nv_bfloat162 h23 = __floats2bfloat162_rn(c2, c3);
            __nv_bfloat162 l01 = __floats2bfloat162_rn(
                c0 - __bfloat162float(h01.x), c1 - __bfloat162float(h01.y));
            __nv_bfloat162 l23 = __floats2bfloat162_rn(
                c2 - __bfloat162float(h23.x), c3 - __bfloat162float(h23.y));
            *(uint32_t*)&OH[o][(size_t)mrow * HD + ncol]       = *(uint32_t*)&h01;
            *(uint32_t*)&OL[o][(size_t)mrow * HD + ncol]       = *(uint32_t*)&l01;
            *(uint32_t*)&OH[o][(size_t)(mrow + 8) * HD + ncol] = *(uint32_t*)&h23;
            *(uint32_t*)&OL[o][(size_t)(mrow + 8) * HD + ncol] = *(uint32_t*)&l23;
        }
    }
}

// ---------------------------------------------------------------------------
// Kernel 2: causal flash attention on HMMA (bf16 hi/lo, fp32 softmax/accum).
// Grid 256 CTAs = 4 batches x 64 q-tiles (64 rows), qt descending in bid for
// LPT scheduling. 128 threads = 4 warps x 16 rows. K/V tiles in smem, P stays
// in registers (c-frag == a-frag layout).
// ---------------------------------------------------------------------------
#define ABROW 144
#define ATILE (64*ABROW)          // 9216 bytes per tile array
#define ATTN_SMEM (4*ATILE)       // Kh,Kl,Vh,Vl = 36864

__global__ __launch_bounds__(128) void attn_mma(float* __restrict__ out)
{
    char* smem = hx_smem;
    const uint32_t sb = smem_u32(smem);
    const int tid  = threadIdx.x;
    const int wid  = tid >> 5;
    const int lane = tid & 31;
    const int g    = lane >> 2;
    const int tg   = lane & 3;

    const int b  = blockIdx.x & 3;
    const int qt = 63 - (blockIdx.x >> 2);    // big tiles first
    const int r0 = qt * 64;
    const size_t tb = (size_t)b * SEQ;

    // ldmatrix lane addressing
    const int lq  = lane >> 3, lr = lane & 7;
    const int bn  = (lq >> 1) * 8 + lr;       // non-trans B: n row
    const int bk  = (lq & 1) * 8;             //               k offset
    const int trr = (lq & 1) * 8 + lr;        // trans: source row (k)
    const int trc = (lq >> 1) * 8;            //        source col (n)

    const int row_a = r0 + wid * 16 + g;      // global rows this thread owns
    const int row_b = row_a + 8;

    // ---- Q a-frags (hi/lo), loaded once from gmem ----
    uint32_t aQh[4][4], aQl[4][4];
    #pragma unroll
    for (int ks = 0; ks < 4; ks++) {
        size_t ra = (tb + row_a) * HD + ks * 16 + 2 * tg;
        size_t rb = (tb + row_b) * HD + ks * 16 + 2 * tg;
        aQh[ks][0] = *(const uint32_t*)&g_qh[ra];
        aQh[ks][1] = *(const uint32_t*)&g_qh[rb];
        aQh[ks][2] = *(const uint32_t*)&g_qh[ra + 8];
        aQh[ks][3] = *(const uint32_t*)&g_qh[rb + 8];
        aQl[ks][0] = *(const uint32_t*)&g_ql[ra];
        aQl[ks][1] = *(const uint32_t*)&g_ql[rb];
        aQl[ks][2] = *(const uint32_t*)&g_ql[ra + 8];
        aQl[ks][3] = *(const uint32_t*)&g_ql[rb + 8];
    }

    float oacc[8][4] = {};
    float mA = -1e30f, mB = -1e30f, lA = 0.0f, lB = 0.0f;

    const __nv_bfloat16* bases[4] = {g_kh + tb * HD, g_kl + tb * HD,
                                     g_vh + tb * HD, g_vl + tb * HD};

    for (int jt = 0; jt <= qt; jt++) {
        const int s0 = jt * 64;
        __syncthreads();
        // ---- stage Kh,Kl,Vh,Vl tiles (64x64 bf16 each) ----
        {
            const int lrow = tid >> 3, lseg = tid & 7;
            #pragma unroll
            for (int i = 0; i < 16; i++) {
                int arr = i >> 2;
                int row = (i & 3) * 16 + lrow;
                *(uint4*)(smem + arr * ATILE + row * ABROW + lseg * 16) =
                    *(const uint4*)(bases[arr] + (size_t)(s0 + row) * HD + lseg * 8);
            }
        }
        __syncthreads();

        // ---- S = Q K^T (3-term hi/lo) ----
        float sacc[8][4] = {};
        #pragma unroll
        for (int ks = 0; ks < 4; ks++) {
            #pragma unroll
            for (int np = 0; np < 4; np++) {
                uint32_t boff = (uint32_t)((np * 16 + bn) * ABROW +
                                           (ks * 16 + bk) * 2);
                uint32_t bh[4], bl[4];
                ldsm_x4(bh, sb + 0 * ATILE + boff);
                ldsm_x4(bl, sb + 1 * ATILE + boff);
                mma16816(sacc[2*np],   aQh[ks], bh);
                mma16816(sacc[2*np+1], aQh[ks], bh + 2);
                mma16816(sacc[2*np],   aQl[ks], bh);
                mma16816(sacc[2*np+1], aQl[ks], bh + 2);
                mma16816(sacc[2*np],   aQh[ks], bl);
                mma16816(sacc[2*np+1], aQh[ks], bl + 2);
            }
        }

        // ---- scale + causal mask (diag tile only) ----
        const float scale = 0.03125f;   // 1/sqrt(1024)
        if (jt == qt) {
            #pragma unroll
            for (int nt = 0; nt < 8; nt++) {
                int col = s0 + nt * 8 + 2 * tg;
                sacc[nt][0] = (col     > row_a) ? -1e30f : sacc[nt][0] * scale;
                sacc[nt][1] = (col + 1 > row_a) ? -1e30f : sacc[nt][1] * scale;
                sacc[nt][2] = (col     > row_b) ? -1e30f : sacc[nt][2] * scale;
                sacc[nt][3] = (col + 1 > row_b) ? -1e30f : sacc[nt][3] * scale;
            }
        } else {
            #pragma unroll
            for (int nt = 0; nt < 8; nt++) {
                sacc[nt][0] *= scale; sacc[nt][1] *= scale;
                sacc[nt][2] *= scale; sacc[nt][3] *= scale;
            }
        }

        // ---- online softmax ----
        float rmA = -1e30f, rmB = -1e30f;
        #pragma unroll
        for (int nt = 0; nt < 8; nt++) {
            rmA = fmaxf(rmA, fmaxf(sacc[nt][0], sacc[nt][1]));
            rmB = fmaxf(rmB, fmaxf(sacc[nt][2], sacc[nt][3]));
        }
        rmA = fmaxf(rmA, __shfl_xor_sync(0xffffffffu, rmA, 1));
        rmA = fmaxf(rmA, __shfl_xor_sync(0xffffffffu, rmA, 2));
        rmB = fmaxf(rmB, __shfl_xor_sync(0xffffffffu, rmB, 1));
        rmB = fmaxf(rmB, __shfl_xor_sync(0xffffffffu, rmB, 2));

        float mnA = fmaxf(mA, rmA), mnB = fmaxf(mB, rmB);
        float alA = __expf(mA - mnA), alB = __expf(mB - mnB);
        mA = mnA; mB = mnB;

        float rsA = 0.0f, rsB = 0.0f;
        uint32_t aPh[4][4], aPl[4][4];
        #pragma unroll
        for (int s4 = 0; s4 < 4; s4++) {
            #pragma unroll
            for (int j = 0; j < 2; j++) {
                int nt = 2 * s4 + j;
                float p0 = __expf(sacc[nt][0] - mA);
                float p1 = __expf(sacc[nt][1] - mA);
                float p2 = __expf(sacc[nt][2] - mB);
                float p3 = __expf(sacc[nt][3] - mB);
                rsA += p0 + p1; rsB += p2 + p3;
                __nv_bfloat162 h01 = __floats2bfloat162_rn(p0, p1);
                __nv_bfloat162 h23 = __floats2bfloat162_rn(p2, p3);
                aPh[s4][2*j]   = *(uint32_t*)&h01;
                aPh[s4][2*j+1] = *(uint32_t*)&h23;
                aPl[s4][2*j]   = pack_bf2(p0 - __bfloat162float(h01.x),
                                          p1 - __bfloat162float(h01.y));
                aPl[s4][2*j+1] = pack_bf2(p2 - __bfloat162float(h23.x),
                                          p3 - __bfloat162float(h23.y));
            }
        }
        rsA += __shfl_xor_sync(0xffffffffu, rsA, 1);
        rsA += __shfl_xor_sync(0xffffffffu, rsA, 2);
        rsB += __shfl_xor_sync(0xffffffffu, rsB, 1);
        rsB += __shfl_xor_sync(0xffffffffu, rsB, 2);
        lA = lA * alA + rsA;
        lB = lB * alB + rsB;

        #pragma unroll
        for (int ht = 0; ht < 8; ht++) {
            oacc[ht][0] *= alA; oacc[ht][1] *= alA;
            oacc[ht][2] *= alB; oacc[ht][3] *= alB;
        }

        // ---- O += P V (3-term hi/lo), V b-frags via ldmatrix.trans ----
        #pragma unroll
        for (int ks = 0; ks < 4; ks++) {
            #pragma unroll
            for (int hp = 0; hp < 4; hp++) {
                uint32_t taddr = sb + 2 * ATILE +
                    (uint32_t)((ks * 16 + trr) * ABROW + (hp * 16 + trc) * 2);
                uint32_t vh4[4], vl4[4];
                ldsm_x4_t(vh4, taddr);
                ldsm_x4_t(vl4, taddr + ATILE);
                mma16816(oacc[2*hp],   aPh[ks], vh4);
                mma16816(oacc[2*hp+1], aPh[ks], vh4 + 2);
                mma16816(oacc[2*hp],   aPl[ks], vh4);
                mma16816(oacc[2*hp+1], aPl[ks], vh4 + 2);
                mma16816(oacc[2*hp],   aPh[ks], vl4);
                mma16816(oacc[2*hp+1], aPh[ks], vl4 + 2);
            }
        }
    }

    // ---- normalize + store ----
    float invA = 1.0f / lA, invB = 1.0f / lB;
    float* ob = out + tb * HD;
    #pragma unroll
    for (int ht = 0; ht < 8; ht++) {
        int col = ht * 8 + 2 * tg;
        *(float2*)&ob[(size_t)row_a * HD + col] =
            make_float2(oacc[ht][0] * invA, oacc[ht][1] * invA);
        *(float2*)&ob[(size_t)row_b * HD + col] =
            make_float2(oacc[ht][2] * invB, oacc[ht][3] * invB);
    }
}

// ---------------------------------------------------------------------------
extern "C" void kernel_launch(void* const* d_in, const int* in_sizes, int n_in,
                              void* d_out, int out_size)
{
    const float* x  = (const float*)d_in[0];
    const float* Wq = (const float*)d_in[1];
    const float* Wk = (const float*)d_in[2];
    const float* Wv = (const float*)d_in[3];
    float* out = (float*)d_out;

    cudaFuncSetAttribute(qkv_mma,
                         cudaFuncAttributeMaxDynamicSharedMemorySize, QKV_SMEM);

    qkv_mma<<<MTOT / 128, 256, QKV_SMEM>>>(x, Wq, Wk, Wv);
    attn_mma<<<BATCH * 64, 128, ATTN_SMEM>>>(out);
}